// round 17
// baseline (speedup 1.0000x reference)
#include <cuda_runtime.h>
#include <cuda_bf16.h>
#include <math.h>
#include <stdint.h>

// Problem constants (fixed shapes)
#define BB 4
#define TT 128
#define DD 768
#define HH 770
#define LL 40
#define PP (TT*TT)
#define NROWS (BB*TT)       // 512
#define RS 784              // padded row stride for g_A

#define KC 128
#define NCH 6
#define C_CHUNK_BYTES 32768
#define B_CHUNK_BYTES 10240
#define DYN_BYTES (2*C_CHUNK_BYTES + 2*B_CHUNK_BYTES)  // 86016
#define NB 256

#define W1S 832             // padded bf16 row stride for g_W1b
// conv units: 4 elements (2 bf16x2) each
#define UX  (NROWS * DD / 4)          // 98304
#define UW1 (2 * DD * (W1S / 4))      // 319488
#define UW2 (DD * LL / 4)             // 7680
#define UCONV (UX + UW1 + UW2)        // 425472
#define UQ ((UCONV + 3) / 4)          // 106368

// Scratch
__device__ __align__(16) float g_A[NROWS * RS];
__device__ __align__(16) __nv_bfloat16 g_Cb[NROWS * DD];
__device__ __align__(16) float g_Ct[NROWS * 2];
__device__ __align__(16) __nv_bfloat16 g_W2b[DD * LL];
__device__ __align__(16) __nv_bfloat16 g_Xb[NROWS * DD];
__device__ __align__(16) __nv_bfloat16 g_W1b[2 * DD * W1S];
__device__ float g_M[BB * LL * TT];
__device__ float g_S[BB * LL * TT];
__device__ int g_in = 0;
__device__ int g_out = 0;

__device__ __forceinline__ uint32_t smem_u32(const void* p) {
    uint32_t a;
    asm("{ .reg .u64 t; cvta.to.shared.u64 t, %1; cvt.u32.u64 %0, t; }" : "=r"(a) : "l"(p));
    return a;
}
__device__ __forceinline__ __nv_bfloat162 u2b(uint32_t u) {
    return *reinterpret_cast<__nv_bfloat162*>(&u);
}
__device__ __forceinline__ uint32_t b2u(__nv_bfloat162 b) {
    return *reinterpret_cast<uint32_t*>(&b);
}
__device__ __forceinline__ uint32_t f2bx2(float lo, float hi) {
    uint32_t u;
    asm("cvt.rn.bf16x2.f32 %0, %1, %2;" : "=r"(u) : "f"(hi), "f"(lo));
    return u;
}
__device__ __forceinline__ uint32_t lds32(uint32_t addr) {
    uint32_t v;
    asm volatile("ld.shared.b32 %0, [%1];" : "=r"(v) : "r"(addr));
    return v;
}
__device__ __forceinline__ uint2 lds64(uint32_t addr) {
    uint2 v;
    asm volatile("ld.shared.v2.b32 {%0,%1}, [%2];" : "=r"(v.x), "=r"(v.y) : "r"(addr));
    return v;
}
#define CP_ASYNC16(dst, src) asm volatile("cp.async.cg.shared.global [%0], [%1], 16;" :: "r"(dst), "l"(src) : "memory")
#define CP_COMMIT()          asm volatile("cp.async.commit_group;" ::: "memory")
#define CP_WAIT(n)           asm volatile("cp.async.wait_group %0;" :: "n"(n) : "memory")

// ---------------------------------------------------------------------------
// Kernel 0: vectorized conversions, 4 independent units per thread (MLP=4).
// ---------------------------------------------------------------------------
__device__ __forceinline__ void conv_one(int u,
        const float* __restrict__ hidden,
        const float* __restrict__ W1,
        const float* __restrict__ W2)
{
    if (u < UX) {
        int r = u / (DD / 4), c = u % (DD / 4);
        int b = r >> 7, t = r & 127;
        float4 v = *(const float4*)(hidden + ((size_t)(b * (TT + 1) + t + 1)) * DD + c * 4);
        uint2 o = { f2bx2(v.x, v.y), f2bx2(v.z, v.w) };
        ((uint2*)g_Xb)[r * (DD / 4) + c] = o;
    } else if (u < UX + UW1) {
        int q = u - UX;
        int r = q / (W1S / 4), p4 = q % (W1S / 4);
        int n0 = p4 * 4;
        float v0, v1, v2, v3;
        if (n0 + 3 < HH) {
            float2 a = *(const float2*)(W1 + (size_t)r * HH + n0);
            float2 c = *(const float2*)(W1 + (size_t)r * HH + n0 + 2);
            v0 = a.x; v1 = a.y; v2 = c.x; v3 = c.y;
        } else {
            v0 = (n0 + 0 < HH) ? W1[(size_t)r * HH + n0 + 0] : 0.f;
            v1 = (n0 + 1 < HH) ? W1[(size_t)r * HH + n0 + 1] : 0.f;
            v2 = (n0 + 2 < HH) ? W1[(size_t)r * HH + n0 + 2] : 0.f;
            v3 = (n0 + 3 < HH) ? W1[(size_t)r * HH + n0 + 3] : 0.f;
        }
        uint2 o = { f2bx2(v0, v1), f2bx2(v2, v3) };
        ((uint2*)g_W1b)[r * (W1S / 4) + p4] = o;
    } else if (u < UCONV) {
        int q = u - UX - UW1;
        float4 v = *(const float4*)(W2 + q * 4);
        uint2 o = { f2bx2(v.x, v.y), f2bx2(v.z, v.w) };
        ((uint2*)g_W2b)[q] = o;
    }
}

__global__ void conv_kernel(const float* __restrict__ hidden,
                            const float* __restrict__ W1,
                            const float* __restrict__ W2)
{
    int u = blockIdx.x * 256 + threadIdx.x;
    conv_one(u, hidden, W1, W2);
    conv_one(u + UQ, hidden, W1, W2);
    conv_one(u + 2 * UQ, hidden, W1, W2);
    conv_one(u + 3 * UQ, hidden, W1, W2);
}

// ---------------------------------------------------------------------------
// Kernel 1: W1 GEMM, 208 CTAs of 64m x 64n, bf16 mma.sync, cp.async dbuf.
// ---------------------------------------------------------------------------
__global__ void __launch_bounds__(256) gemm_w1_bf16_kernel(const float* __restrict__ b1)
{
    const int u = blockIdx.x;
    const bool isC = (u & 1);
    const int rest = u >> 1;
    const int bn = (rest % 13) * 64;
    const int bm = (rest / 13) * 64;
    const char* XsrcB = (const char*)g_Xb + (size_t)bm * (DD * 2);
    const char* WsrcB = (const char*)(g_W1b + (isC ? (size_t)DD * W1S : 0)) + (size_t)bn * 2;

    __shared__ __align__(16) unsigned char sXb[2][64 * 80];    // 2 x 5120
    __shared__ __align__(16) unsigned char sWb[2][32 * 144];   // 2 x 4608

    const int tid = threadIdx.x;
    const int wid = tid >> 5;
    const int lid = tid & 31;
    const int m0 = (wid & 3) * 16;
    const int nh = wid >> 2;
    const int gq = lid >> 2;
    const int tg = lid & 3;
    const uint32_t bHalf = (lid >> 3) & 1;

    const uint32_t sX0 = smem_u32(&sXb[0][0]);
    const uint32_t sW0 = smem_u32(&sWb[0][0]);

    float acc[4][4] = {};

    {
        int row = tid >> 2, ch = tid & 3;
        CP_ASYNC16(sX0 + (uint32_t)(row * 80 + ch * 16),
                   XsrcB + (size_t)row * (DD * 2) + ch * 16);
        int krow = tid >> 3, ch8 = tid & 7;
        CP_ASYNC16(sW0 + (uint32_t)(krow * 144 + ch8 * 16),
                   WsrcB + (size_t)krow * (W1S * 2) + ch8 * 16);
        CP_COMMIT();
    }

    for (int cc = 0; cc < 24; cc++) {
        if (cc < 23) {
            const int p = (cc + 1) & 1;
            const int kk = (cc + 1) * 32;
            int row = tid >> 2, ch = tid & 3;
            CP_ASYNC16(sX0 + (uint32_t)(p * 5120 + row * 80 + ch * 16),
                       XsrcB + (size_t)row * (DD * 2) + kk * 2 + ch * 16);
            int krow = tid >> 3, ch8 = tid & 7;
            CP_ASYNC16(sW0 + (uint32_t)(p * 4608 + krow * 144 + ch8 * 16),
                       WsrcB + (size_t)(kk + krow) * (W1S * 2) + ch8 * 16);
            CP_COMMIT();
            CP_WAIT(1);
        } else {
            CP_WAIT(0);
        }
        __syncthreads();

        const uint32_t xBuf = sX0 + (uint32_t)((cc & 1) * 5120);
        const uint32_t wBuf = sW0 + (uint32_t)((cc & 1) * 4608);
        const uint32_t aBase = xBuf + (uint32_t)((m0 + (lid & 15)) * 80 + (lid >> 4) * 16);

        #pragma unroll
        for (int ks = 0; ks < 2; ks++) {
            uint32_t a0, a1, a2, a3;
            asm volatile("ldmatrix.sync.aligned.m8n8.x4.shared.b16 {%0,%1,%2,%3}, [%4];"
                : "=r"(a0), "=r"(a1), "=r"(a2), "=r"(a3)
                : "r"(aBase + (uint32_t)(ks * 32)));
            const uint32_t bRowBase = wBuf + (uint32_t)((ks * 16 + bHalf * 8 + (lid & 7)) * 144 + nh * 64);
            #pragma unroll
            for (int nt = 0; nt < 4; nt++) {
                uint32_t b0, b1v;
                asm volatile("ldmatrix.sync.aligned.m8n8.x2.trans.shared.b16 {%0,%1}, [%2];"
                    : "=r"(b0), "=r"(b1v) : "r"(bRowBase + (uint32_t)(nt * 16)));
                asm volatile("mma.sync.aligned.m16n8k16.row.col.f32.bf16.bf16.f32 "
                    "{%0,%1,%2,%3}, {%4,%5,%6,%7}, {%8,%9}, {%0,%1,%2,%3};"
                    : "+f"(acc[nt][0]), "+f"(acc[nt][1]), "+f"(acc[nt][2]), "+f"(acc[nt][3])
                    : "r"(a0), "r"(a1), "r"(a2), "r"(a3), "r"(b0), "r"(b1v));
            }
        }
        __syncthreads();
    }

    #pragma unroll
    for (int half = 0; half < 2; half++) {
        int gm = bm + m0 + gq + half * 8;
        #pragma unroll
        for (int nt = 0; nt < 4; nt++) {
            int gn = bn + nh * 32 + nt * 8 + tg * 2;
            float v0 = acc[nt][half * 2 + 0];
            float v1 = acc[nt][half * 2 + 1];
            if (!isC) {
                if (gn < HH)     g_A[(size_t)gm * RS + gn]     = v0;
                if (gn + 1 < HH) g_A[(size_t)gm * RS + gn + 1] = v1;
            } else {
                if (gn < DD) {
                    float w0 = v0 + b1[gn], w1 = v1 + b1[gn + 1];
                    *(uint32_t*)(g_Cb + (size_t)gm * DD + gn) = f2bx2(w0, w1);
                } else if (gn < HH) {  // gn == 768
                    g_Ct[gm * 2 + 0] = v0 + b1[768];
                    g_Ct[gm * 2 + 1] = v1 + b1[769];
                }
            }
        }
    }
}

// ---------------------------------------------------------------------------
// Kernel 2: fused pair kernel.  A/wl staged in ks-interleaved layout so the
// mainloop uses LDS.64 (pairs p and p+4 adjacent).  Otherwise round-16 exact.
// ---------------------------------------------------------------------------
__global__ void __launch_bounds__(256, 2) fused_pair_kernel(
        const float* __restrict__ W1,
        const float* __restrict__ W2,
        const float* __restrict__ b2,
        const int*   __restrict__ pred_spans,
        const int*   __restrict__ span_avail,
        float* __restrict__ out)
{
    extern __shared__ __align__(16) unsigned char dynsmem[];
    unsigned char* sC = dynsmem;
    unsigned char* sB = dynsmem + 2 * C_CHUNK_BYTES;

    __shared__ uint32_t sAb[2][384];
    __shared__ uint32_t sWlb[384];
    __shared__ uint32_t sIndP0[TT], sIndP1[TT];
    __shared__ float sW2a[LL], sW2b[LL], sB2[LL];
    __shared__ float sLSE[LL];

    const int tid = threadIdx.x;
    const int wid = tid >> 5;
    const int lid = tid & 31;
    const int bi2 = blockIdx.x;
    const int b = bi2 >> 6;
    const int ip = bi2 & 63;
    const int i0 = ip * 2;
    const int i1 = ip * 2 + 1;
    const int bTT = b * TT;

    const float* Arow0 = g_A + (size_t)(bTT + i0) * RS;
    const float* Arow1 = g_A + (size_t)(bTT + i1) * RS;
    const float* wlrow = W1 + (size_t)(2 * DD) * HH;

    const uint32_t sC_base = smem_u32(sC);
    const uint32_t sB_base = smem_u32(sB);
    const char* cSrcBase = (const char*)(g_Cb + (size_t)bTT * DD);
    const char* bSrcBase = (const char*)g_W2b;

    {
        #pragma unroll
        for (int q = 0; q < 8; q++) {
            int e = tid + q * 256;
            int row = e >> 4, ch = e & 15;
            CP_ASYNC16(sC_base + (uint32_t)(row * 256 + ((ch ^ (row & 7)) << 4)),
                       cSrcBase + (size_t)row * (DD * 2) + ch * 16);
        }
        for (int e = tid; e < 640; e += 256) {
            int k = e / 5, nt = e % 5;
            int blockb = ((k >> 4) * 2 + ((k >> 3) & 1)) * 5 + nt;
            CP_ASYNC16(sB_base + (uint32_t)(blockb * 128 + (k & 7) * 16),
                       bSrcBase + (size_t)k * (LL * 2) + nt * 16);
        }
        CP_COMMIT();
    }

    if (tid < TT) {
        int s = pred_spans[b * 2 + 0];
        int e = pred_spans[b * 2 + 1];
        int j = tid;
        bool f0 = (i0 == s) && (j == e);
        bool in0 = (s <= i0) && (i0 <= j) && (j <= e) && !f0;
        float d0 = f0 ? 2.f : (in0 ? 1.f : 0.f);
        sIndP0[j] = f2bx2(d0, d0);
        bool f1 = (i1 == s) && (j == e);
        bool in1 = (s <= i1) && (i1 <= j) && (j <= e) && !f1;
        float d1 = f1 ? 2.f : (in1 ? 1.f : 0.f);
        sIndP1[j] = f2bx2(d1, d1);
    }
    if (tid < LL) {
        sW2a[tid] = W2[(size_t)768 * LL + tid];
        sW2b[tid] = W2[(size_t)769 * LL + tid];
        sB2[tid]  = b2[tid];
    }
    // A/wl staging with ks-interleaved permutation:
    // pair p (0..63 within chunk) -> pos = (p>>3)*8 + (p&3)*2 + ((p>>2)&1)
    for (int e = tid; e < 384; e += 256) {
        int p = e & 63;
        int pos = (e & ~63) | (((p >> 3) << 3) | ((p & 3) << 1) | ((p >> 2) & 1));
        float2 v0 = *(const float2*)(Arow0 + e * 2);
        float2 v1 = *(const float2*)(Arow1 + e * 2);
        float2 w  = *(const float2*)(wlrow + e * 2);
        sAb[0][pos] = f2bx2(v0.x, v0.y);
        sAb[1][pos] = f2bx2(v1.x, v1.y);
        sWlb[pos]   = f2bx2(w.x, w.y);
    }
    __syncthreads();

    const int gq = lid >> 2;
    const int tg = lid & 3;
    const int jlo = wid * 16 + gq;
    const int jhi = jlo + 8;
    const uint32_t bHalf = (lid >> 3) & 1;
    const uint32_t bRow  = (lid & 7) * 16;
    const uint32_t d0lo = sIndP0[jlo], d0hi = sIndP0[jhi];
    const uint32_t d1lo = sIndP1[jlo], d1hi = sIndP1[jhi];
    const __nv_bfloat162 zero2 = __float2bfloat162_rn(0.f);
    const uint32_t sAb0_base = smem_u32(&sAb[0][0]);
    const uint32_t sAb1_base = smem_u32(&sAb[1][0]);
    const uint32_t sWl_base  = smem_u32(&sWlb[0]);
    const uint32_t cRowLo = (uint32_t)(jlo * 256 + tg * 4);
    const uint32_t cRowHi = (uint32_t)(jhi * 256 + tg * 4);
    const int swLo = jlo & 7, swHi = jhi & 7;

    float acc[2][5][4] = {};

    for (int cc = 0; cc < NCH; cc++) {
        if (cc < NCH - 1) {
            const int p = (cc + 1) & 1;
            const char* src = cSrcBase + (size_t)(cc + 1) * (KC * 2);
            #pragma unroll
            for (int q = 0; q < 8; q++) {
                int e = tid + q * 256;
                int row = e >> 4, ch = e & 15;
                CP_ASYNC16(sC_base + (uint32_t)(p * C_CHUNK_BYTES + row * 256 + ((ch ^ (row & 7)) << 4)),
                           src + (size_t)row * (DD * 2) + ch * 16);
            }
            const char* bsrc = bSrcBase + (size_t)(cc + 1) * KC * (LL * 2);
            for (int e = tid; e < 640; e += 256) {
                int k = e / 5, nt = e % 5;
                int blockb = ((k >> 4) * 2 + ((k >> 3) & 1)) * 5 + nt;
                CP_ASYNC16(sB_base + (uint32_t)(p * B_CHUNK_BYTES + blockb * 128 + (k & 7) * 16),
                           bsrc + (size_t)k * (LL * 2) + nt * 16);
            }
            CP_COMMIT();
            CP_WAIT(1);
        } else {
            CP_WAIT(0);
        }
        __syncthreads();

        const uint32_t cBuf = sC_base + (uint32_t)((cc & 1) * C_CHUNK_BYTES);
        const uint32_t bBuf = sB_base + (uint32_t)((cc & 1) * B_CHUNK_BYTES);
        const uint32_t aIdx = (uint32_t)(cc * 64 * 4);

        #pragma unroll
        for (int ks = 0; ks < 8; ks++) {
            const uint32_t aoff = aIdx + (uint32_t)((ks * 8 + tg * 2) * 4);
            const uint2 aV0 = lds64(sAb0_base + aoff);
            const uint2 aV1 = lds64(sAb1_base + aoff);
            const uint2 wV  = lds64(sWl_base + aoff);
            const uint32_t c_ll = lds32(cBuf + cRowLo + (uint32_t)((((2 * ks)     ^ swLo)) << 4));
            const uint32_t c_hl = lds32(cBuf + cRowHi + (uint32_t)((((2 * ks)     ^ swHi)) << 4));
            const uint32_t c_lh = lds32(cBuf + cRowLo + (uint32_t)((((2 * ks + 1) ^ swLo)) << 4));
            const uint32_t c_hh = lds32(cBuf + cRowHi + (uint32_t)((((2 * ks + 1) ^ swHi)) << 4));
            uint32_t a00 = b2u(__hmax2(__hfma2(u2b(d0lo), u2b(wV.x), __hadd2(u2b(aV0.x), u2b(c_ll))), zero2));
            uint32_t a01 = b2u(__hmax2(__hfma2(u2b(d0hi), u2b(wV.x), __hadd2(u2b(aV0.x), u2b(c_hl))), zero2));
            uint32_t a02 = b2u(__hmax2(__hfma2(u2b(d0lo), u2b(wV.y), __hadd2(u2b(aV0.y), u2b(c_lh))), zero2));
            uint32_t a03 = b2u(__hmax2(__hfma2(u2b(d0hi), u2b(wV.y), __hadd2(u2b(aV0.y), u2b(c_hh))), zero2));
            uint32_t a10 = b2u(__hmax2(__hfma2(u2b(d1lo), u2b(wV.x), __hadd2(u2b(aV1.x), u2b(c_ll))), zero2));
            uint32_t a11 = b2u(__hmax2(__hfma2(u2b(d1hi), u2b(wV.x), __hadd2(u2b(aV1.x), u2b(c_hl))), zero2));
            uint32_t a12 = b2u(__hmax2(__hfma2(u2b(d1lo), u2b(wV.y), __hadd2(u2b(aV1.y), u2b(c_lh))), zero2));
            uint32_t a13 = b2u(__hmax2(__hfma2(u2b(d1hi), u2b(wV.y), __hadd2(u2b(aV1.y), u2b(c_hh))), zero2));
            #pragma unroll
            for (int nt = 0; nt < 5; nt++) {
                uint32_t b0, b1v;
                uint32_t baddr = bBuf + (uint32_t)(((ks * 2 + bHalf) * 5 + nt) * 128) + bRow;
                asm volatile("ldmatrix.sync.aligned.m8n8.x2.trans.shared.b16 {%0,%1}, [%2];"
                    : "=r"(b0), "=r"(b1v) : "r"(baddr));
                asm volatile("mma.sync.aligned.m16n8k16.row.col.f32.bf16.bf16.f32 "
                    "{%0,%1,%2,%3}, {%4,%5,%6,%7}, {%8,%9}, {%0,%1,%2,%3};"
                    : "+f"(acc[0][nt][0]), "+f"(acc[0][nt][1]), "+f"(acc[0][nt][2]), "+f"(acc[0][nt][3])
                    : "r"(a00), "r"(a01), "r"(a02), "r"(a03), "r"(b0), "r"(b1v));
                asm volatile("mma.sync.aligned.m16n8k16.row.col.f32.bf16.bf16.f32 "
                    "{%0,%1,%2,%3}, {%4,%5,%6,%7}, {%8,%9}, {%0,%1,%2,%3};"
                    : "+f"(acc[1][nt][0]), "+f"(acc[1][nt][1]), "+f"(acc[1][nt][2]), "+f"(acc[1][nt][3])
                    : "r"(a10), "r"(a11), "r"(a12), "r"(a13), "r"(b0), "r"(b1v));
            }
        }
        __syncthreads();
    }

    // ---- epilogue: logits in vv, LSE partials ----
    float vv[2][2][10];
    {
        const int lcol = tg * 2;
        const float wl768 = wlrow[768], wl769 = wlrow[769];
        #pragma unroll
        for (int ii = 0; ii < 2; ii++) {
            const float* Ar = ii ? Arow1 : Arow0;
            const uint32_t* sI = ii ? sIndP1 : sIndP0;
            const int iv = ii ? i1 : i0;
            const float a768 = Ar[768], a769 = Ar[769];
            #pragma unroll
            for (int half = 0; half < 2; half++) {
                const int j = wid * 16 + gq + half * 8;
                const float ind = __bfloat162float(u2b(sI[j]).x);
                const float2 ct = *(const float2*)(g_Ct + (size_t)(bTT + j) * 2);
                const float h768 = fmaxf(fmaf(ind, wl768, a768 + ct.x), 0.f);
                const float h769 = fmaxf(fmaf(ind, wl769, a769 + ct.y), 0.f);
                const bool msk = span_avail[iv * TT + j] >= 1;
                #pragma unroll
                for (int nt = 0; nt < 5; nt++) {
                    const int col = nt * 8 + lcol;
                    float r0 = acc[ii][nt][half * 2 + 0];
                    float r1 = acc[ii][nt][half * 2 + 1];
                    vv[ii][half][nt * 2 + 0] = msk ? (r0 + sB2[col]     + h768 * sW2a[col]     + h769 * sW2b[col])     : 0.f;
                    vv[ii][half][nt * 2 + 1] = msk ? (r1 + sB2[col + 1] + h768 * sW2a[col + 1] + h769 * sW2b[col + 1]) : 0.f;
                }
            }
        }
    }
    float* sRm = (float*)sC;
    float* sRs = sRm + 2 * 8 * LL;
    #pragma unroll
    for (int ii = 0; ii < 2; ii++) {
        #pragma unroll
        for (int c = 0; c < 10; c++) {
            float m = fmaxf(vv[ii][0][c], vv[ii][1][c]);
            m = fmaxf(m, __shfl_xor_sync(0xffffffffu, m, 4));
            m = fmaxf(m, __shfl_xor_sync(0xffffffffu, m, 8));
            m = fmaxf(m, __shfl_xor_sync(0xffffffffu, m, 16));
            float s = __expf(vv[ii][0][c] - m) + __expf(vv[ii][1][c] - m);
            s += __shfl_xor_sync(0xffffffffu, s, 4);
            s += __shfl_xor_sync(0xffffffffu, s, 8);
            s += __shfl_xor_sync(0xffffffffu, s, 16);
            if (lid < 4) {
                int col = (c >> 1) * 8 + (lid & 3) * 2 + (c & 1);
                sRm[(ii * 8 + wid) * LL + col] = m;
                sRs[(ii * 8 + wid) * LL + col] = s;
            }
        }
    }
    __syncthreads();
    if (tid < 2 * LL) {
        const int ii = tid / LL, l = tid % LL;
        const int iv = ii ? i1 : i0;
        float m = sRm[ii * 8 * LL + l];
        #pragma unroll
        for (int w = 1; w < 8; w++) m = fmaxf(m, sRm[(ii * 8 + w) * LL + l]);
        float s = 0.f;
        #pragma unroll
        for (int w = 0; w < 8; w++) s += sRs[(ii * 8 + w) * LL + l] * __expf(sRm[(ii * 8 + w) * LL + l] - m);
        g_M[(b * LL + l) * TT + iv] = m;
        g_S[(b * LL + l) * TT + iv] = s;
    }

    // ---- device-wide barrier (256 CTAs co-resident at 2/SM) ----
    __syncthreads();
    if (tid == 0) {
        __threadfence();
        atomicAdd(&g_in, 1);
        while (*(volatile int*)&g_in < NB) { }
    }
    __syncthreads();
    __threadfence();

    // ---- LSE for batch b ----
    #pragma unroll
    for (int q = 0; q < 5; q++) {
        const int l = wid * 5 + q;
        const float* Mr = g_M + (size_t)(b * LL + l) * TT;
        const float* Sr = g_S + (size_t)(b * LL + l) * TT;
        float m = -INFINITY, s = 0.f;
        #pragma unroll
        for (int t = 0; t < 4; t++) {
            float m2 = Mr[lid + 32 * t];
            float s2 = Sr[lid + 32 * t];
            float mn = fmaxf(m, m2);
            s = s * __expf(m - mn) + s2 * __expf(m2 - mn);
            m = mn;
        }
        #pragma unroll
        for (int off = 16; off > 0; off >>= 1) {
            float m2 = __shfl_xor_sync(0xffffffffu, m, off);
            float s2 = __shfl_xor_sync(0xffffffffu, s, off);
            float mn = fmaxf(m, m2);
            s = s * __expf(m - mn) + s2 * __expf(m2 - mn);
            m = mn;
        }
        if (lid == 0) sLSE[l] = m + logf(s);
    }
    __syncthreads();

    // ---- final store: out = vv - lse ----
    {
        const int lcol = tg * 2;
        #pragma unroll
        for (int ii = 0; ii < 2; ii++) {
            const int iv = ii ? i1 : i0;
            #pragma unroll
            for (int half = 0; half < 2; half++) {
                const int j = wid * 16 + gq + half * 8;
                float* orow = out + ((size_t)(b * PP + iv * TT + j)) * LL;
                #pragma unroll
                for (int nt = 0; nt < 5; nt++) {
                    const int col = nt * 8 + lcol;
                    float2 v;
                    v.x = vv[ii][half][nt * 2 + 0] - sLSE[col];
                    v.y = vv[ii][half][nt * 2 + 1] - sLSE[col + 1];
                    *(float2*)(orow + col) = v;
                }
            }
        }
    }

    // ---- reset counters for next graph replay ----
    if (tid == 0) {
        int old = atomicAdd(&g_out, 1);
        if (old == NB - 1) {
            g_in = 0;
            g_out = 0;
            __threadfence();
        }
    }
}

// ---------------------------------------------------------------------------
extern "C" void kernel_launch(void* const* d_in, const int* in_sizes, int n_in,
                              void* d_out, int out_size)
{
    const float* hidden     = (const float*)d_in[0];
    const float* W1         = (const float*)d_in[1];
    const float* b1         = (const float*)d_in[2];
    const float* W2         = (const float*)d_in[3];
    const float* b2         = (const float*)d_in[4];
    const int*   pred_spans = (const int*)d_in[5];
    const int*   span_avail = (const int*)d_in[6];
    float* out = (float*)d_out;

    cudaFuncSetAttribute(fused_pair_kernel, cudaFuncAttributeMaxDynamicSharedMemorySize, DYN_BYTES);

    conv_kernel<<<(UQ + 255) / 256, 256>>>(hidden, W1, W2);
    gemm_w1_bf16_kernel<<<208, 256>>>(b1);
    fused_pair_kernel<<<NB, 256, DYN_BYTES>>>(W1, W2, b2, pred_spans, span_avail, out);
}